// round 13
// baseline (speedup 1.0000x reference)
#include <cuda_runtime.h>
#include <cstdint>
#include <math.h>

#define NN 200000
#define NE 800000
#define NG 8192
#define H  128
#define NL 3
#define KX 78
#define BN_EPS 1e-5f

#define TM 64
#define NTILES (NN / TM)       // 3125 exact
#define GRID_SM 148
#define WS 132                 // node padded stride: conflict-free
#define EWS 84                 // enc padded stride
#define GRID_ENC 296           // 2 blocks/SM
#define NT_THREADS 512

// ---------------- scratch (device globals: no allocation allowed) ----------------
__device__ float g_h  [NN * H];
__device__ float g_agg[NN * H];
__device__ float g_Wt [NL * 2 * H * H];
__device__ float g_pool[NG * H];
__device__ int   g_cnt [NG];

// ---------------- helpers ----------------
__device__ __forceinline__ void red4(float* addr, float4 v) {
    asm volatile("red.global.add.v4.f32 [%0], {%1,%2,%3,%4};"
                 :: "l"(addr), "f"(v.x), "f"(v.y), "f"(v.z), "f"(v.w) : "memory");
}
__device__ __forceinline__ unsigned tf32_rna(float f) {
    unsigned u;
    asm("cvt.rna.tf32.f32 %0, %1;" : "=r"(u) : "f"(f));
    return u;
}
__device__ __forceinline__ void mma_tf32(float* c, const unsigned* a, unsigned b0, unsigned b1) {
    asm volatile(
        "mma.sync.aligned.m16n8k8.row.col.f32.tf32.tf32.f32 "
        "{%0,%1,%2,%3}, {%4,%5,%6,%7}, {%8,%9}, {%0,%1,%2,%3};"
        : "+f"(c[0]), "+f"(c[1]), "+f"(c[2]), "+f"(c[3])
        : "r"(a[0]), "r"(a[1]), "r"(a[2]), "r"(a[3]), "r"(b0), "r"(b1));
}
__device__ __forceinline__ void cp_async16(void* smem, const void* g) {
    unsigned s = (unsigned)__cvta_generic_to_shared(smem);
    asm volatile("cp.async.cg.shared.global [%0], [%1], 16;" :: "r"(s), "l"(g) : "memory");
}
#define CP_COMMIT() asm volatile("cp.async.commit_group;" ::: "memory")
#define CP_WAIT0()  asm volatile("cp.async.wait_group 0;" ::: "memory")

// ---------------- prep: transpose + tf32-round all layer weights ----------------
__global__ void prep_w_kernel(const float* __restrict__ W1, const float* __restrict__ W2) {
    int i = blockIdx.x * blockDim.x + threadIdx.x;
    if (i >= NL * H * H) return;
    int l = i / (H * H), r = i % (H * H);
    int k = r >> 7, n = r & 127;
    g_Wt[(2 * l)     * H * H + n * H + k] = __uint_as_float(tf32_rna(W1[i]));
    g_Wt[(2 * l + 1) * H * H + n * H + k] = __uint_as_float(tf32_rna(W2[i]));
}

// ---------------- zero pool ----------------
__global__ void zero_pool_kernel() {
    int i = blockIdx.x * blockDim.x + threadIdx.x;
    if (i < NG * H / 4) ((float4*)g_pool)[i] = make_float4(0.f, 0.f, 0.f, 0.f);
    if (i < NG) g_cnt[i] = 0;
}

// ---------------- tensor-core encoder (R12 winner, unchanged) ----------------
#define ENC_SMEM ((H * EWS + TM * EWS + H) * 4)
__global__ void __launch_bounds__(256, 2)
enc_tc_kernel(const float* __restrict__ x,
              const float* __restrict__ Wenc,
              const float* __restrict__ benc) {
    extern __shared__ float sm[];
    float* Wts = sm;
    float* Xs  = sm + H * EWS;
    float* bs  = Xs + TM * EWS;
    int tid = threadIdx.x;

    for (int i = tid; i < H * 80; i += 256) {
        int n = i / 80, k = i - (i / 80) * 80;
        Wts[n * EWS + k] = (k < KX) ? __uint_as_float(tf32_rna(Wenc[k * H + n])) : 0.f;
    }
    if (tid < H) bs[tid] = benc[tid];

    int wid = tid >> 5, lane = tid & 31;
    int rm = (wid & 1) * 32;
    int cn = (wid >> 1) * 32;
    int g = lane >> 2, t = lane & 3;

    for (int tile = blockIdx.x; tile < NTILES; tile += GRID_ENC) {
        __syncthreads();
        int base = tile * TM;
        for (int i = tid; i < TM * 80; i += 256) {
            int row = i / 80, k = i - (i / 80) * 80;
            float v = (k < KX) ? x[(base + row) * KX + k] : 0.f;
            Xs[row * EWS + k] = __uint_as_float(tf32_rna(v));
        }
        __syncthreads();

        float acc[2][4][4];
        #pragma unroll
        for (int mt = 0; mt < 2; mt++)
            #pragma unroll
            for (int nt = 0; nt < 4; nt++)
                #pragma unroll
                for (int j = 0; j < 4; j++) acc[mt][nt][j] = 0.f;

        #pragma unroll
        for (int ks = 0; ks < 10; ks++) {
            int k0 = ks * 8;
            unsigned a[2][4];
            #pragma unroll
            for (int mt = 0; mt < 2; mt++) {
                const float* Ar = Xs + (rm + mt * 16 + g) * EWS + k0 + t;
                a[mt][0] = __float_as_uint(Ar[0]);
                a[mt][1] = __float_as_uint(Ar[8 * EWS]);
                a[mt][2] = __float_as_uint(Ar[4]);
                a[mt][3] = __float_as_uint(Ar[8 * EWS + 4]);
            }
            #pragma unroll
            for (int nt = 0; nt < 4; nt++) {
                const float* Br = Wts + (cn + nt * 8 + g) * EWS + k0 + t;
                unsigned b0 = __float_as_uint(Br[0]);
                unsigned b1 = __float_as_uint(Br[4]);
                mma_tf32(acc[0][nt], a[0], b0, b1);
                mma_tf32(acc[1][nt], a[1], b0, b1);
            }
        }

        #pragma unroll
        for (int mt = 0; mt < 2; mt++) {
            int r0 = base + rm + mt * 16 + g;
            #pragma unroll
            for (int nt = 0; nt < 4; nt++) {
                int col = cn + nt * 8 + 2 * t;
                float bx = bs[col], by = bs[col + 1];
                float2 o0 = make_float2(acc[mt][nt][0] + bx, acc[mt][nt][1] + by);
                float2 o1 = make_float2(acc[mt][nt][2] + bx, acc[mt][nt][3] + by);
                *(float2*)&g_h[r0 * H + col]         = o0;
                *(float2*)&g_h[(r0 + 8) * H + col]   = o1;
                *(float2*)&g_agg[r0 * H + col]       = o0;
                *(float2*)&g_agg[(r0 + 8) * H + col] = o1;
            }
        }
    }
}

// ---------------- edge kernel (R6/R12 measured best, unchanged) ----------------
__global__ void edge_kernel(const int*   __restrict__ ei,
                            const float* __restrict__ ea,
                            const float* __restrict__ We,
                            const float* __restrict__ be) {
    __shared__ float Wes[10 * H];
    __shared__ float bes[H];
    int tid = threadIdx.x;
    for (int i = tid; i < 10 * H; i += blockDim.x) Wes[i] = We[i];
    if (tid < H) bes[tid] = be[tid];
    __syncthreads();

    int warp = tid >> 5, lane = tid & 31;
    int c0 = 4 * lane;
    int e0 = blockIdx.x * 32 + warp;

    int src[4], dst[4];
    float eav[4];
    #pragma unroll
    for (int t = 0; t < 4; t++) {
        int e = e0 + t * 8;
        src[t] = ei[e];
        dst[t] = ei[NE + e];
        eav[t] = (lane < 10) ? ea[e * 10 + lane] : 0.f;
    }
    float4 hv[4];
    #pragma unroll
    for (int t = 0; t < 4; t++) hv[t] = *(const float4*)&g_h[src[t] * H + c0];

    #pragma unroll
    for (int t = 0; t < 4; t++) {
        float4 acc = *(const float4*)&bes[c0];
        #pragma unroll
        for (int k = 0; k < 10; k++) {
            float ek = __shfl_sync(0xffffffffu, eav[t], k);
            float4 wv = *(const float4*)&Wes[k * H + c0];
            acc.x += ek * wv.x; acc.y += ek * wv.y;
            acc.z += ek * wv.z; acc.w += ek * wv.w;
        }
        float4 m;
        m.x = fmaxf(hv[t].x + acc.x, 0.f);
        m.y = fmaxf(hv[t].y + acc.y, 0.f);
        m.z = fmaxf(hv[t].z + acc.z, 0.f);
        m.w = fmaxf(hv[t].w + acc.w, 0.f);
        red4(&g_agg[dst[t] * H + c0], m);
    }
}

// ---------------- persistent tensor-core node kernel: 512 thr, K-SPLIT warp pairs ----------------
// 16 warps: kh = wid>>3 (k-half), sub = wid&7 -> rm=(sub&1)*32, cn=(sub>>1)*32.
// Each 32x32 output tile computed by a warp pair; partials reduced via the idle Z buffer.
#define NODE_SMEM ((2 * H * WS + 2 * TM * WS + 4 * H) * 4)

template<bool CVT>
__device__ __forceinline__ void tc_gemm_half(const float* __restrict__ As,
                                             const float* __restrict__ Bs,
                                             float acc[2][4][4],
                                             int rm, int cn, int g, int t, int kbase) {
    #pragma unroll
    for (int ks = 0; ks < 8; ks++) {
        int k0 = kbase + ks * 8;
        unsigned a[2][4];
        #pragma unroll
        for (int mt = 0; mt < 2; mt++) {
            const float* Ar = As + (rm + mt * 16 + g) * WS + k0 + t;
            float f0 = Ar[0], f1 = Ar[8 * WS], f2 = Ar[4], f3 = Ar[8 * WS + 4];
            if (CVT) {
                a[mt][0] = tf32_rna(f0); a[mt][1] = tf32_rna(f1);
                a[mt][2] = tf32_rna(f2); a[mt][3] = tf32_rna(f3);
            } else {
                a[mt][0] = __float_as_uint(f0); a[mt][1] = __float_as_uint(f1);
                a[mt][2] = __float_as_uint(f2); a[mt][3] = __float_as_uint(f3);
            }
        }
        #pragma unroll
        for (int nt = 0; nt < 4; nt++) {
            const float* Br = Bs + (cn + nt * 8 + g) * WS + k0 + t;
            unsigned b0 = __float_as_uint(Br[0]);
            unsigned b1 = __float_as_uint(Br[4]);
            mma_tf32(acc[0][nt], a[0], b0, b1);
            mma_tf32(acc[1][nt], a[1], b0, b1);
        }
    }
}

__device__ __forceinline__ void store_partials(float* S, const float acc[2][4][4],
                                               int rm, int cn, int g, int t) {
    #pragma unroll
    for (int mt = 0; mt < 2; mt++) {
        int r0 = rm + mt * 16 + g;
        #pragma unroll
        for (int nt = 0; nt < 4; nt++) {
            int col = cn + nt * 8 + 2 * t;
            *(float2*)&S[r0 * WS + col]       = make_float2(acc[mt][nt][0], acc[mt][nt][1]);
            *(float2*)&S[(r0 + 8) * WS + col] = make_float2(acc[mt][nt][2], acc[mt][nt][3]);
        }
    }
}

__global__ void __launch_bounds__(NT_THREADS, 1)
node_tc_kernel(int layer,
               const float* __restrict__ b1, const float* __restrict__ b2,
               const float* __restrict__ gamma, const float* __restrict__ beta,
               int seed_agg) {
    extern __shared__ float sm[];
    float* W1s = sm;                       // [128][WS]
    float* W2s = sm + H * WS;
    float* Z0  = sm + 2 * H * WS;          // [64][WS] double buffer (Z / scratch / T)
    float* Z1  = Z0 + TM * WS;
    float* b1s = Z1 + TM * WS;
    float* b2s = b1s + H;
    float* gs  = b2s + H;
    float* bts = gs + H;

    int tid = threadIdx.x;

    {
        const float4* w1g = (const float4*)(g_Wt + (2 * layer) * H * H);
        const float4* w2g = (const float4*)(g_Wt + (2 * layer + 1) * H * H);
        for (int i = tid; i < H * H / 4; i += NT_THREADS) {
            int n = i >> 5, k = (i & 31) * 4;
            float4 v1 = w1g[i], v2 = w2g[i];
            float* p1 = &W1s[n * WS + k];
            p1[0] = v1.x; p1[1] = v1.y; p1[2] = v1.z; p1[3] = v1.w;
            float* p2 = &W2s[n * WS + k];
            p2[0] = v2.x; p2[1] = v2.y; p2[2] = v2.z; p2[3] = v2.w;
        }
        if (tid < H) {
            b1s[tid] = b1[tid];
            b2s[tid] = b2[tid];
            gs[tid]  = gamma[tid] * rsqrtf(1.f + BN_EPS);
            bts[tid] = beta[tid];
        }
    }

    int wid = tid >> 5, lane = tid & 31;
    int kh  = wid >> 3;            // 0: k 0-63, 1: k 64-127
    int sub = wid & 7;
    int rm = (sub & 1) * 32;
    int cn = (sub >> 1) * 32;
    int g = lane >> 2, t = lane & 3;
    int kbase = kh * 64;

    float* Zb[2] = { Z0, Z1 };
    int tile = blockIdx.x;
    {
        const float* src = g_agg + (size_t)tile * TM * H;
        #pragma unroll
        for (int j = 0; j < 4; j++) {
            int idx = tid + j * NT_THREADS;
            int row = idx >> 5, c4 = idx & 31;
            cp_async16(&Zb[0][row * WS + c4 * 4], src + idx * 4);
        }
    }
    CP_COMMIT();

    int buf = 0;
    for (; tile < NTILES; tile += GRID_SM) {
        float* cur = Zb[buf];
        float* oth = Zb[buf ^ 1];

        CP_WAIT0();
        __syncthreads();     // cur holds Z; all prior reads of cur/oth done

        float acc[2][4][4];
        #pragma unroll
        for (int mt = 0; mt < 2; mt++)
            #pragma unroll
            for (int nt = 0; nt < 4; nt++)
                #pragma unroll
                for (int j = 0; j < 4; j++) acc[mt][nt][j] = 0.f;

        // GEMM1 partials over this warp's k-half (rounding A in-register)
        tc_gemm_half<true>(cur, W1s, acc, rm, cn, g, t, kbase);
        __syncthreads();

        if (kh == 1) store_partials(oth, acc, rm, cn, g, t);
        __syncthreads();

        if (kh == 0) {
            // reduce + bias + relu + tf32 -> T (into cur; Z fully consumed)
            #pragma unroll
            for (int mt = 0; mt < 2; mt++) {
                int r0 = rm + mt * 16 + g;
                #pragma unroll
                for (int nt = 0; nt < 4; nt++) {
                    int col = cn + nt * 8 + 2 * t;
                    float2 p0 = *(const float2*)&oth[r0 * WS + col];
                    float2 p1 = *(const float2*)&oth[(r0 + 8) * WS + col];
                    float2 o0, o1;
                    o0.x = __uint_as_float(tf32_rna(fmaxf(acc[mt][nt][0] + p0.x + b1s[col], 0.f)));
                    o0.y = __uint_as_float(tf32_rna(fmaxf(acc[mt][nt][1] + p0.y + b1s[col + 1], 0.f)));
                    o1.x = __uint_as_float(tf32_rna(fmaxf(acc[mt][nt][2] + p1.x + b1s[col], 0.f)));
                    o1.y = __uint_as_float(tf32_rna(fmaxf(acc[mt][nt][3] + p1.y + b1s[col + 1], 0.f)));
                    *(float2*)&cur[r0 * WS + col]       = o0;
                    *(float2*)&cur[(r0 + 8) * WS + col] = o1;
                }
            }
        }
        __syncthreads();     // T complete; oth scratch fully consumed

        // Prefetch next tile into oth (overlaps GEMM2)
        int ntile = tile + GRID_SM;
        if (ntile < NTILES) {
            const float* src = g_agg + (size_t)ntile * TM * H;
            #pragma unroll
            for (int j = 0; j < 4; j++) {
                int idx = tid + j * NT_THREADS;
                int row = idx >> 5, c4 = idx & 31;
                cp_async16(&oth[row * WS + c4 * 4], src + idx * 4);
            }
        }
        CP_COMMIT();

        #pragma unroll
        for (int mt = 0; mt < 2; mt++)
            #pragma unroll
            for (int nt = 0; nt < 4; nt++)
                #pragma unroll
                for (int j = 0; j < 4; j++) acc[mt][nt][j] = 0.f;

        // GEMM2 partials (T already tf32-rounded)
        tc_gemm_half<false>(cur, W2s, acc, rm, cn, g, t, kbase);
        __syncthreads();     // all reads of T done

        if (kh == 1) store_partials(cur, acc, rm, cn, g, t);   // T dead -> scratch
        __syncthreads();

        if (kh == 0) {
            #pragma unroll
            for (int mt = 0; mt < 2; mt++) {
                int r0l = rm + mt * 16 + g;
                int r0 = tile * TM + r0l;
                #pragma unroll
                for (int nt = 0; nt < 4; nt++) {
                    int col = cn + nt * 8 + 2 * t;
                    float2 p0 = *(const float2*)&cur[r0l * WS + col];
                    float2 p1 = *(const float2*)&cur[(r0l + 8) * WS + col];
                    float gx = gs[col], gy = gs[col + 1];
                    float bx = bts[col], by = bts[col + 1];
                    float2 o0, o1;
                    o0.x = fmaxf((acc[mt][nt][0] + p0.x + b2s[col])     * gx + bx, 0.f);
                    o0.y = fmaxf((acc[mt][nt][1] + p0.y + b2s[col + 1]) * gy + by, 0.f);
                    o1.x = fmaxf((acc[mt][nt][2] + p1.x + b2s[col])     * gx + bx, 0.f);
                    o1.y = fmaxf((acc[mt][nt][3] + p1.y + b2s[col + 1]) * gy + by, 0.f);
                    *(float2*)&g_h[r0 * H + col]       = o0;
                    *(float2*)&g_h[(r0 + 8) * H + col] = o1;
                    if (seed_agg) {
                        *(float2*)&g_agg[r0 * H + col]       = o0;
                        *(float2*)&g_agg[(r0 + 8) * H + col] = o1;
                    }
                }
            }
        }
        buf ^= 1;   // oth (prefetched Z) becomes cur
    }
}

// ---------------- pool ----------------
__global__ void pool_kernel(const int* __restrict__ batch) {
    int gw   = (blockIdx.x * blockDim.x + threadIdx.x) >> 5;
    int lane = threadIdx.x & 31;
    if (gw >= NN) return;
    int g = batch[gw];
    float4 hv = *(const float4*)&g_h[gw * H + 4 * lane];
    red4(&g_pool[g * H + 4 * lane], hv);
    if (lane == 0) atomicAdd(&g_cnt[g], 1);
}

// ---------------- head ----------------
__global__ void head_kernel(const float* __restrict__ Wh1, const float* __restrict__ bh1,
                            const float* __restrict__ Wh2, const float* __restrict__ bh2,
                            float* __restrict__ out) {
    __shared__ float W1s[H * 64];
    __shared__ float W2s[64];
    int tid = threadIdx.x;
    for (int i = tid; i < H * 64; i += blockDim.x) W1s[i] = Wh1[i];
    if (tid < 64) W2s[tid] = Wh2[tid];
    __syncthreads();

    int warp = tid >> 5, lane = tid & 31;
    int g = blockIdx.x * 8 + warp;
    if (g >= NG) return;

    float inv = 1.f / fmaxf((float)g_cnt[g], 1.f);
    float4 pv = *(const float4*)&g_pool[g * H + 4 * lane];
    pv.x *= inv; pv.y *= inv; pv.z *= inv; pv.w *= inv;

    float a0 = bh1[lane], a1 = bh1[lane + 32];
    #pragma unroll
    for (int k = 0; k < H; k++) {
        int m = k & 3;
        float comp = (m == 0) ? pv.x : (m == 1) ? pv.y : (m == 2) ? pv.z : pv.w;
        float p = __shfl_sync(0xffffffffu, comp, k >> 2);
        a0 += p * W1s[k * 64 + lane];
        a1 += p * W1s[k * 64 + lane + 32];
    }
    a0 = fmaxf(a0, 0.f);
    a1 = fmaxf(a1, 0.f);
    float s = a0 * W2s[lane] + a1 * W2s[lane + 32];
    #pragma unroll
    for (int off = 16; off; off >>= 1) s += __shfl_down_sync(0xffffffffu, s, off);
    if (lane == 0) out[g] = 1.f / (1.f + expf(-(s + bh2[0])));
}

// ---------------- launch ----------------
extern "C" void kernel_launch(void* const* d_in, const int* in_sizes, int n_in,
                              void* d_out, int out_size) {
    const float* x     = (const float*)d_in[0];
    const int*   ei    = (const int*)  d_in[1];
    const float* ea    = (const float*)d_in[2];
    const int*   batch = (const int*)  d_in[3];
    const float* Wenc  = (const float*)d_in[4];
    const float* benc  = (const float*)d_in[5];
    const float* We    = (const float*)d_in[6];
    const float* be    = (const float*)d_in[7];
    const float* W1    = (const float*)d_in[8];
    const float* b1    = (const float*)d_in[9];
    const float* W2    = (const float*)d_in[10];
    const float* b2    = (const float*)d_in[11];
    const float* gamma = (const float*)d_in[12];
    const float* beta  = (const float*)d_in[13];
    const float* Wh1   = (const float*)d_in[14];
    const float* bh1   = (const float*)d_in[15];
    const float* Wh2   = (const float*)d_in[16];
    const float* bh2   = (const float*)d_in[17];
    float* out = (float*)d_out;

    cudaFuncSetAttribute(enc_tc_kernel,  cudaFuncAttributeMaxDynamicSharedMemorySize, ENC_SMEM);
    cudaFuncSetAttribute(node_tc_kernel, cudaFuncAttributeMaxDynamicSharedMemorySize, NODE_SMEM);

    zero_pool_kernel<<<(NG * H / 4 + 255) / 256, 256>>>();
    prep_w_kernel<<<(NL * H * H + 255) / 256, 256>>>(W1, W2);
    enc_tc_kernel<<<GRID_ENC, 256, ENC_SMEM>>>(x, Wenc, benc);

    for (int l = 0; l < NL; l++) {
        edge_kernel<<<NE / 32, 256>>>(ei, ea, We + l * 10 * H, be + l * H);
        node_tc_kernel<<<GRID_SM, NT_THREADS, NODE_SMEM>>>(
            l, b1 + l * H, b2 + l * H, gamma + l * H, beta + l * H, (l < NL - 1) ? 1 : 0);
    }

    pool_kernel<<<(NN + 7) / 8, 256>>>(batch);
    head_kernel<<<(NG + 7) / 8, 256>>>(Wh1, bh1, Wh2, bh2, out);
}

// round 14
// speedup vs baseline: 1.1519x; 1.1519x over previous
#include <cuda_runtime.h>
#include <cstdint>
#include <math.h>

#define NN 200000
#define NE 800000
#define NG 8192
#define H  128
#define NL 3
#define KX 78
#define BN_EPS 1e-5f

#define TM 64
#define NTILES (NN / TM)       // 3125 exact
#define GRID_SM 148
#define WS 132                 // node padded stride: conflict-free
#define EWS 84                 // enc padded stride
#define GRID_ENC 296           // 2 blocks/SM
#define NT_THREADS 512

// ---------------- scratch (device globals: no allocation allowed) ----------------
__device__ float g_h  [NN * H];
__device__ float g_agg[NN * H];
__device__ float g_Wt [NL * 2 * H * H];
__device__ float g_pool[NG * H];
__device__ int   g_cnt [NG];

// ---------------- helpers ----------------
__device__ __forceinline__ void red4(float* addr, float4 v) {
    asm volatile("red.global.add.v4.f32 [%0], {%1,%2,%3,%4};"
                 :: "l"(addr), "f"(v.x), "f"(v.y), "f"(v.z), "f"(v.w) : "memory");
}
__device__ __forceinline__ unsigned tf32_rna(float f) {
    unsigned u;
    asm("cvt.rna.tf32.f32 %0, %1;" : "=r"(u) : "f"(f));
    return u;
}
__device__ __forceinline__ void mma_tf32(float* c, const unsigned* a, unsigned b0, unsigned b1) {
    asm volatile(
        "mma.sync.aligned.m16n8k8.row.col.f32.tf32.tf32.f32 "
        "{%0,%1,%2,%3}, {%4,%5,%6,%7}, {%8,%9}, {%0,%1,%2,%3};"
        : "+f"(c[0]), "+f"(c[1]), "+f"(c[2]), "+f"(c[3])
        : "r"(a[0]), "r"(a[1]), "r"(a[2]), "r"(a[3]), "r"(b0), "r"(b1));
}
__device__ __forceinline__ void cp_async16(void* smem, const void* g) {
    unsigned s = (unsigned)__cvta_generic_to_shared(smem);
    asm volatile("cp.async.cg.shared.global [%0], [%1], 16;" :: "r"(s), "l"(g) : "memory");
}
#define CP_COMMIT() asm volatile("cp.async.commit_group;" ::: "memory")
#define CP_WAIT0()  asm volatile("cp.async.wait_group 0;" ::: "memory")
#define BAR_GRP(id) asm volatile("bar.sync %0, 256;" :: "r"(id) : "memory")

// ---------------- prep: transpose + tf32-round all layer weights ----------------
__global__ void prep_w_kernel(const float* __restrict__ W1, const float* __restrict__ W2) {
    int i = blockIdx.x * blockDim.x + threadIdx.x;
    if (i >= NL * H * H) return;
    int l = i / (H * H), r = i % (H * H);
    int k = r >> 7, n = r & 127;
    g_Wt[(2 * l)     * H * H + n * H + k] = __uint_as_float(tf32_rna(W1[i]));
    g_Wt[(2 * l + 1) * H * H + n * H + k] = __uint_as_float(tf32_rna(W2[i]));
}

// ---------------- zero pool ----------------
__global__ void zero_pool_kernel() {
    int i = blockIdx.x * blockDim.x + threadIdx.x;
    if (i < NG * H / 4) ((float4*)g_pool)[i] = make_float4(0.f, 0.f, 0.f, 0.f);
    if (i < NG) g_cnt[i] = 0;
}

// ---------------- tensor-core encoder (R12 winner, unchanged) ----------------
#define ENC_SMEM ((H * EWS + TM * EWS + H) * 4)
__global__ void __launch_bounds__(256, 2)
enc_tc_kernel(const float* __restrict__ x,
              const float* __restrict__ Wenc,
              const float* __restrict__ benc) {
    extern __shared__ float sm[];
    float* Wts = sm;
    float* Xs  = sm + H * EWS;
    float* bs  = Xs + TM * EWS;
    int tid = threadIdx.x;

    for (int i = tid; i < H * 80; i += 256) {
        int n = i / 80, k = i - (i / 80) * 80;
        Wts[n * EWS + k] = (k < KX) ? __uint_as_float(tf32_rna(Wenc[k * H + n])) : 0.f;
    }
    if (tid < H) bs[tid] = benc[tid];

    int wid = tid >> 5, lane = tid & 31;
    int rm = (wid & 1) * 32;
    int cn = (wid >> 1) * 32;
    int g = lane >> 2, t = lane & 3;

    for (int tile = blockIdx.x; tile < NTILES; tile += GRID_ENC) {
        __syncthreads();
        int base = tile * TM;
        for (int i = tid; i < TM * 80; i += 256) {
            int row = i / 80, k = i - (i / 80) * 80;
            float v = (k < KX) ? x[(base + row) * KX + k] : 0.f;
            Xs[row * EWS + k] = __uint_as_float(tf32_rna(v));
        }
        __syncthreads();

        float acc[2][4][4];
        #pragma unroll
        for (int mt = 0; mt < 2; mt++)
            #pragma unroll
            for (int nt = 0; nt < 4; nt++)
                #pragma unroll
                for (int j = 0; j < 4; j++) acc[mt][nt][j] = 0.f;

        #pragma unroll
        for (int ks = 0; ks < 10; ks++) {
            int k0 = ks * 8;
            unsigned a[2][4];
            #pragma unroll
            for (int mt = 0; mt < 2; mt++) {
                const float* Ar = Xs + (rm + mt * 16 + g) * EWS + k0 + t;
                a[mt][0] = __float_as_uint(Ar[0]);
                a[mt][1] = __float_as_uint(Ar[8 * EWS]);
                a[mt][2] = __float_as_uint(Ar[4]);
                a[mt][3] = __float_as_uint(Ar[8 * EWS + 4]);
            }
            #pragma unroll
            for (int nt = 0; nt < 4; nt++) {
                const float* Br = Wts + (cn + nt * 8 + g) * EWS + k0 + t;
                unsigned b0 = __float_as_uint(Br[0]);
                unsigned b1 = __float_as_uint(Br[4]);
                mma_tf32(acc[0][nt], a[0], b0, b1);
                mma_tf32(acc[1][nt], a[1], b0, b1);
            }
        }

        #pragma unroll
        for (int mt = 0; mt < 2; mt++) {
            int r0 = base + rm + mt * 16 + g;
            #pragma unroll
            for (int nt = 0; nt < 4; nt++) {
                int col = cn + nt * 8 + 2 * t;
                float bx = bs[col], by = bs[col + 1];
                float2 o0 = make_float2(acc[mt][nt][0] + bx, acc[mt][nt][1] + by);
                float2 o1 = make_float2(acc[mt][nt][2] + bx, acc[mt][nt][3] + by);
                *(float2*)&g_h[r0 * H + col]         = o0;
                *(float2*)&g_h[(r0 + 8) * H + col]   = o1;
                *(float2*)&g_agg[r0 * H + col]       = o0;
                *(float2*)&g_agg[(r0 + 8) * H + col] = o1;
            }
        }
    }
}

// ---------------- edge kernel (measured best, unchanged) ----------------
__global__ void edge_kernel(const int*   __restrict__ ei,
                            const float* __restrict__ ea,
                            const float* __restrict__ We,
                            const float* __restrict__ be) {
    __shared__ float Wes[10 * H];
    __shared__ float bes[H];
    int tid = threadIdx.x;
    for (int i = tid; i < 10 * H; i += blockDim.x) Wes[i] = We[i];
    if (tid < H) bes[tid] = be[tid];
    __syncthreads();

    int warp = tid >> 5, lane = tid & 31;
    int c0 = 4 * lane;
    int e0 = blockIdx.x * 32 + warp;

    int src[4], dst[4];
    float eav[4];
    #pragma unroll
    for (int t = 0; t < 4; t++) {
        int e = e0 + t * 8;
        src[t] = ei[e];
        dst[t] = ei[NE + e];
        eav[t] = (lane < 10) ? ea[e * 10 + lane] : 0.f;
    }
    float4 hv[4];
    #pragma unroll
    for (int t = 0; t < 4; t++) hv[t] = *(const float4*)&g_h[src[t] * H + c0];

    #pragma unroll
    for (int t = 0; t < 4; t++) {
        float4 acc = *(const float4*)&bes[c0];
        #pragma unroll
        for (int k = 0; k < 10; k++) {
            float ek = __shfl_sync(0xffffffffu, eav[t], k);
            float4 wv = *(const float4*)&Wes[k * H + c0];
            acc.x += ek * wv.x; acc.y += ek * wv.y;
            acc.z += ek * wv.z; acc.w += ek * wv.w;
        }
        float4 m;
        m.x = fmaxf(hv[t].x + acc.x, 0.f);
        m.y = fmaxf(hv[t].y + acc.y, 0.f);
        m.z = fmaxf(hv[t].z + acc.z, 0.f);
        m.w = fmaxf(hv[t].w + acc.w, 0.f);
        red4(&g_agg[dst[t] * H + c0], m);
    }
}

// ---------------- persistent tensor-core node kernel: 512 thr = 2 independent tile groups ----------------
// Each group of 256 threads = the proven R6 engine (2m x 4n warps, 64-row tile, T reuses Z buffer).
// Group g owns Z buffer g and processes tiles (2*blockIdx.x + g), stepping 296.
// Group-local sync via named barriers; cross-group overlap hides Z-load latency.
#define NODE_SMEM ((2 * H * WS + 2 * TM * WS + 4 * H) * 4)

template<bool CVT>
__device__ __forceinline__ void tc_gemm64(const float* __restrict__ As,
                                          const float* __restrict__ Bs,
                                          float acc[2][4][4],
                                          int rm, int cn, int g, int t) {
    #pragma unroll 4
    for (int ks = 0; ks < 16; ks++) {
        int k0 = ks * 8;
        unsigned a[2][4];
        #pragma unroll
        for (int mt = 0; mt < 2; mt++) {
            const float* Ar = As + (rm + mt * 16 + g) * WS + k0 + t;
            float f0 = Ar[0], f1 = Ar[8 * WS], f2 = Ar[4], f3 = Ar[8 * WS + 4];
            if (CVT) {
                a[mt][0] = tf32_rna(f0); a[mt][1] = tf32_rna(f1);
                a[mt][2] = tf32_rna(f2); a[mt][3] = tf32_rna(f3);
            } else {
                a[mt][0] = __float_as_uint(f0); a[mt][1] = __float_as_uint(f1);
                a[mt][2] = __float_as_uint(f2); a[mt][3] = __float_as_uint(f3);
            }
        }
        #pragma unroll
        for (int nt = 0; nt < 4; nt++) {
            const float* Br = Bs + (cn + nt * 8 + g) * WS + k0 + t;
            unsigned b0 = __float_as_uint(Br[0]);
            unsigned b1 = __float_as_uint(Br[4]);
            mma_tf32(acc[0][nt], a[0], b0, b1);
            mma_tf32(acc[1][nt], a[1], b0, b1);
        }
    }
}

__global__ void __launch_bounds__(NT_THREADS, 1)
node_tc_kernel(int layer,
               const float* __restrict__ b1, const float* __restrict__ b2,
               const float* __restrict__ gamma, const float* __restrict__ beta,
               int seed_agg) {
    extern __shared__ float sm[];
    float* W1s = sm;                       // [128][WS]
    float* W2s = sm + H * WS;
    float* Z0  = sm + 2 * H * WS;          // group 0's tile buffer (Z then T)
    float* Z1  = Z0 + TM * WS;             // group 1's tile buffer
    float* b1s = Z1 + TM * WS;
    float* b2s = b1s + H;
    float* gs  = b2s + H;
    float* bts = gs + H;

    int tid = threadIdx.x;

    // Stage weights once (all 512 threads), then full-block sync before groups diverge
    {
        const float4* w1g = (const float4*)(g_Wt + (2 * layer) * H * H);
        const float4* w2g = (const float4*)(g_Wt + (2 * layer + 1) * H * H);
        for (int i = tid; i < H * H / 4; i += NT_THREADS) {
            int n = i >> 5, k = (i & 31) * 4;
            float4 v1 = w1g[i], v2 = w2g[i];
            float* p1 = &W1s[n * WS + k];
            p1[0] = v1.x; p1[1] = v1.y; p1[2] = v1.z; p1[3] = v1.w;
            float* p2 = &W2s[n * WS + k];
            p2[0] = v2.x; p2[1] = v2.y; p2[2] = v2.z; p2[3] = v2.w;
        }
        if (tid < H) {
            b1s[tid] = b1[tid];
            b2s[tid] = b2[tid];
            gs[tid]  = gamma[tid] * rsqrtf(1.f + BN_EPS);
            bts[tid] = beta[tid];
        }
    }
    __syncthreads();

    int grp  = tid >> 8;            // 0 or 1
    int ltid = tid & 255;
    int wid = ltid >> 5, lane = ltid & 31;
    int rm = (wid & 1) * 32;        // 2 m-warps
    int cn = (wid >> 1) * 32;       // 4 n-warps
    int g = lane >> 2, t = lane & 3;
    int barid = 1 + grp;
    float* Zs = grp ? Z1 : Z0;

    for (int tile = blockIdx.x * 2 + grp; tile < NTILES; tile += 2 * GRID_SM) {
        // Load this group's Z tile (group-cooperative)
        {
            const float* src = g_agg + (size_t)tile * TM * H;
            #pragma unroll
            for (int j = 0; j < 8; j++) {
                int idx = ltid + j * 256;            // float4 index in 64x128 tile
                int row = idx >> 5, c4 = idx & 31;
                cp_async16(&Zs[row * WS + c4 * 4], src + idx * 4);
            }
        }
        CP_COMMIT();
        CP_WAIT0();
        BAR_GRP(barid);

        float acc[2][4][4];
        #pragma unroll
        for (int mt = 0; mt < 2; mt++)
            #pragma unroll
            for (int nt = 0; nt < 4; nt++)
                #pragma unroll
                for (int j = 0; j < 4; j++) acc[mt][nt][j] = 0.f;

        // GEMM1: T = relu(Z @ W1 + b1), rounding A in-register
        tc_gemm64<true>(Zs, W1s, acc, rm, cn, g, t);
        BAR_GRP(barid);

        #pragma unroll
        for (int mt = 0; mt < 2; mt++) {
            int r0 = rm + mt * 16 + g;
            #pragma unroll
            for (int nt = 0; nt < 4; nt++) {
                int col = cn + nt * 8 + 2 * t;
                float2 o0, o1;
                o0.x = __uint_as_float(tf32_rna(fmaxf(acc[mt][nt][0] + b1s[col], 0.f)));
                o0.y = __uint_as_float(tf32_rna(fmaxf(acc[mt][nt][1] + b1s[col + 1], 0.f)));
                o1.x = __uint_as_float(tf32_rna(fmaxf(acc[mt][nt][2] + b1s[col], 0.f)));
                o1.y = __uint_as_float(tf32_rna(fmaxf(acc[mt][nt][3] + b1s[col + 1], 0.f)));
                *(float2*)&Zs[r0 * WS + col]       = o0;
                *(float2*)&Zs[(r0 + 8) * WS + col] = o1;
            }
        }
        BAR_GRP(barid);

        #pragma unroll
        for (int mt = 0; mt < 2; mt++)
            #pragma unroll
            for (int nt = 0; nt < 4; nt++)
                #pragma unroll
                for (int j = 0; j < 4; j++) acc[mt][nt][j] = 0.f;

        // GEMM2: Y = T @ W2 + b2 -> BN -> relu
        tc_gemm64<false>(Zs, W2s, acc, rm, cn, g, t);

        #pragma unroll
        for (int mt = 0; mt < 2; mt++) {
            int r0 = tile * TM + rm + mt * 16 + g;
            #pragma unroll
            for (int nt = 0; nt < 4; nt++) {
                int col = cn + nt * 8 + 2 * t;
                float gx = gs[col], gy = gs[col + 1];
                float bx = bts[col], by = bts[col + 1];
                float2 o0, o1;
                o0.x = fmaxf((acc[mt][nt][0] + b2s[col])     * gx + bx, 0.f);
                o0.y = fmaxf((acc[mt][nt][1] + b2s[col + 1]) * gy + by, 0.f);
                o1.x = fmaxf((acc[mt][nt][2] + b2s[col])     * gx + bx, 0.f);
                o1.y = fmaxf((acc[mt][nt][3] + b2s[col + 1]) * gy + by, 0.f);
                *(float2*)&g_h[r0 * H + col]       = o0;
                *(float2*)&g_h[(r0 + 8) * H + col] = o1;
                if (seed_agg) {
                    *(float2*)&g_agg[r0 * H + col]       = o0;
                    *(float2*)&g_agg[(r0 + 8) * H + col] = o1;
                }
            }
        }
        // All group threads must finish reading T before next tile's cp.async overwrites Zs
        BAR_GRP(barid);
    }
}

// ---------------- pool ----------------
__global__ void pool_kernel(const int* __restrict__ batch) {
    int gw   = (blockIdx.x * blockDim.x + threadIdx.x) >> 5;
    int lane = threadIdx.x & 31;
    if (gw >= NN) return;
    int g = batch[gw];
    float4 hv = *(const float4*)&g_h[gw * H + 4 * lane];
    red4(&g_pool[g * H + 4 * lane], hv);
    if (lane == 0) atomicAdd(&g_cnt[g], 1);
}

// ---------------- head ----------------
__global__ void head_kernel(const float* __restrict__ Wh1, const float* __restrict__ bh1,
                            const float* __restrict__ Wh2, const float* __restrict__ bh2,
                            float* __restrict__ out) {
    __shared__ float W1s[H * 64];
    __shared__ float W2s[64];
    int tid = threadIdx.x;
    for (int i = tid; i < H * 64; i += blockDim.x) W1s[i] = Wh1[i];
    if (tid < 64) W2s[tid] = Wh2[tid];
    __syncthreads();

    int warp = tid >> 5, lane = tid & 31;
    int g = blockIdx.x * 8 + warp;
    if (g >= NG) return;

    float inv = 1.f / fmaxf((float)g_cnt[g], 1.f);
    float4 pv = *(const float4*)&g_pool[g * H + 4 * lane];
    pv.x *= inv; pv.y *= inv; pv.z *= inv; pv.w *= inv;

    float a0 = bh1[lane], a1 = bh1[lane + 32];
    #pragma unroll
    for (int k = 0; k < H; k++) {
        int m = k & 3;
        float comp = (m == 0) ? pv.x : (m == 1) ? pv.y : (m == 2) ? pv.z : pv.w;
        float p = __shfl_sync(0xffffffffu, comp, k >> 2);
        a0 += p * W1s[k * 64 + lane];
        a1 += p * W1s[k * 64 + lane + 32];
    }
    a0 = fmaxf(a0, 0.f);
    a1 = fmaxf(a1, 0.f);
    float s = a0 * W2s[lane] + a1 * W2s[lane + 32];
    #pragma unroll
    for (int off = 16; off; off >>= 1) s += __shfl_down_sync(0xffffffffu, s, off);
    if (lane == 0) out[g] = 1.f / (1.f + expf(-(s + bh2[0])));
}

// ---------------- launch ----------------
extern "C" void kernel_launch(void* const* d_in, const int* in_sizes, int n_in,
                              void* d_out, int out_size) {
    const float* x     = (const float*)d_in[0];
    const int*   ei    = (const int*)  d_in[1];
    const float* ea    = (const float*)d_in[2];
    const int*   batch = (const int*)  d_in[3];
    const float* Wenc  = (const float*)d_in[4];
    const float* benc  = (const float*)d_in[5];
    const float* We    = (const float*)d_in[6];
    const float* be    = (const float*)d_in[7];
    const float* W1    = (const float*)d_in[8];
    const float* b1    = (const float*)d_in[9];
    const float* W2    = (const float*)d_in[10];
    const float* b2    = (const float*)d_in[11];
    const float* gamma = (const float*)d_in[12];
    const float* beta  = (const float*)d_in[13];
    const float* Wh1   = (const float*)d_in[14];
    const float* bh1   = (const float*)d_in[15];
    const float* Wh2   = (const float*)d_in[16];
    const float* bh2   = (const float*)d_in[17];
    float* out = (float*)d_out;

    cudaFuncSetAttribute(enc_tc_kernel,  cudaFuncAttributeMaxDynamicSharedMemorySize, ENC_SMEM);
    cudaFuncSetAttribute(node_tc_kernel, cudaFuncAttributeMaxDynamicSharedMemorySize, NODE_SMEM);

    zero_pool_kernel<<<(NG * H / 4 + 255) / 256, 256>>>();
    prep_w_kernel<<<(NL * H * H + 255) / 256, 256>>>(W1, W2);
    enc_tc_kernel<<<GRID_ENC, 256, ENC_SMEM>>>(x, Wenc, benc);

    for (int l = 0; l < NL; l++) {
        edge_kernel<<<NE / 32, 256>>>(ei, ea, We + l * 10 * H, be + l * H);
        node_tc_kernel<<<GRID_SM, NT_THREADS, NODE_SMEM>>>(
            l, b1 + l * H, b2 + l * H, gamma + l * H, beta + l * H, (l < NL - 1) ? 1 : 0);
    }

    pool_kernel<<<(NN + 7) / 8, 256>>>(batch);
    head_kernel<<<(NG + 7) / 8, 256>>>(Wh1, bh1, Wh2, bh2, out);
}